// round 4
// baseline (speedup 1.0000x reference)
#include <cuda_runtime.h>
#include <math.h>

constexpr int H_   = 768;
constexpr int H4   = H_ / 4;     // 192 float4 per row
constexpr int NC_  = 8;          // chunks
constexpr int NL_  = 8921;       // labels
constexpr int NN_  = 4;          // notes
constexpr int JB_  = 1115;       // lw bucket width (8921 = 8*1115 + 1)

constexpr int ESEG  = 8;         // segments per encoding chunk (64 rows each)
constexpr int EROWS = 64;
constexpr int LSEG  = 16;        // segments per lw bucket (~70 rows each)
constexpr int LROWS = 70;        // 16*70 = 1120 >= 1116
constexpr int ENC_BLOCKS = NC_ * ESEG;          // 64
constexpr int LW_BLOCKS  = NC_ * LSEG;          // 128
constexpr int GRID       = ENC_BLOCKS + LW_BLOCKS;  // 192
constexpr int TPB        = 192;  // 192 threads * float4 = 768 columns

__device__ float4 g_pe[NC_ * ESEG * H4];   // encoding partials (fully overwritten each call)
__device__ float4 g_pl[NC_ * LSEG * H4];   // label_weights partials
__device__ unsigned int g_cnt = 0;         // arrival counter (reset by finale -> replay-safe)

__device__ __forceinline__ float4 f4add(float4 a, float4 b) {
    return make_float4(a.x + b.x, a.y + b.y, a.z + b.z, a.w + b.w);
}
__device__ __forceinline__ void f4acc(float4& a, float4 b) {
    a.x += b.x; a.y += b.y; a.z += b.z; a.w += b.w;
}

__global__ __launch_bounds__(TPB) void fused_kernel(const float* __restrict__ encF,
                                                    const float* __restrict__ lwF,
                                                    const void* __restrict__ idsRaw,
                                                    float* __restrict__ out) {
    const float4* enc = (const float4*)encF;
    const float4* lw  = (const float4*)lwF;
    int b = blockIdx.x;
    int t = threadIdx.x;

    // ---------------- Phase 1: streaming column block sums ----------------
    if (b < ENC_BLOCKS) {
        int c = b >> 3, s = b & 7;                       // chunk, segment
        const float4* p = enc + (size_t)(c * 512 + s * EROWS) * H4 + t;
        float4 a0 = make_float4(0,0,0,0), a1 = a0, a2 = a0, a3 = a0;
        #pragma unroll
        for (int r = 0; r < EROWS; r += 4) {
            f4acc(a0, p[(r + 0) * H4]);
            f4acc(a1, p[(r + 1) * H4]);
            f4acc(a2, p[(r + 2) * H4]);
            f4acc(a3, p[(r + 3) * H4]);
        }
        g_pe[(c * ESEG + s) * H4 + t] = f4add(f4add(a0, a1), f4add(a2, a3));
    } else {
        int bb = b - ENC_BLOCKS;
        int c = bb >> 4, s = bb & 15;                    // bucket, segment
        int r0   = c * JB_ + s * LROWS;
        int rend = min(r0 + LROWS, (c == NC_ - 1) ? NL_ : (c + 1) * JB_);
        float4 a0 = make_float4(0,0,0,0), a1 = a0;
        int r = r0;
        for (; r + 2 <= rend; r += 2) {
            f4acc(a0, lw[(size_t)(r + 0) * H4 + t]);
            f4acc(a1, lw[(size_t)(r + 1) * H4 + t]);
        }
        if (r < rend) f4acc(a0, lw[(size_t)r * H4 + t]);
        g_pl[(c * LSEG + s) * H4 + t] = f4add(a0, a1);
    }

    // ---------------- arrival gate: last block runs the finale ----------------
    __threadfence();
    __syncthreads();                 // all threads' partial stores issued before counting
    __shared__ bool isLast;
    if (t == 0) isLast = (atomicAdd(&g_cnt, 1u) == (unsigned)(GRID - 1));
    __syncthreads();
    if (!isLast) return;

    // ---------------- Phase 2 (single block): combine + sigmoid ----------------
    // Per-chunk encoding sums CS[c] and per-bucket lw sums L[c], float4 over h.
    float4 CS[NC_], L[NC_];
    #pragma unroll
    for (int c = 0; c < NC_; ++c) {
        float4 se = make_float4(0,0,0,0);
        #pragma unroll
        for (int s = 0; s < ESEG; ++s) f4acc(se, g_pe[(c * ESEG + s) * H4 + t]);
        CS[c] = se;
        float4 sl = make_float4(0,0,0,0);
        #pragma unroll
        for (int s = 0; s < LSEG; ++s) f4acc(sl, g_pl[(c * LSEG + s) * H4 + t]);
        L[c] = sl;
    }

    // note_end_chunk_ids: detect int64 vs int32 layout
    const int* w = (const int*)idsRaw;
    int ids[NN_];
    {
        bool is64 = true;
        int v[NN_];
        #pragma unroll
        for (int i = 0; i < NN_; ++i) {
            int lo = w[2 * i], hi = w[2 * i + 1];
            v[i] = lo;
            if (hi != 0 || lo < 0 || lo >= NC_) is64 = false;
        }
        #pragma unroll
        for (int i = 0; i + 1 < NN_; ++i)
            if (v[i] > v[i + 1]) is64 = false;
        #pragma unroll
        for (int i = 0; i < NN_; ++i) ids[i] = is64 ? v[i] : w[i];
    }

    // Boundary lw rows: j = 1115k straddles chunks (k-1, k) at prefix P[512k]
    float4 bnd[NC_ - 1];
    #pragma unroll
    for (int k = 1; k < NC_; ++k)
        bnd[k - 1] = lw[(size_t)(JB_ * k) * H4 + t];

    float4 Ptot = make_float4(0,0,0,0);
    #pragma unroll
    for (int c = 0; c < NC_; ++c) f4acc(Ptot, CS[c]);

    float4* out4 = (float4*)out;
    #pragma unroll
    for (int n = 0; n < NN_; ++n) {
        // softmax weight row for this note: masked(n,c) <=> c <= ids[n]
        float Wn[NC_];
        #pragma unroll
        for (int c = 0; c < NC_; ++c) {
            int cnt = 0;
            #pragma unroll
            for (int i = 0; i < NN_; ++i) cnt += (ids[i] < c) ? 1 : 0;
            bool un = (ids[n] < c);
            Wn[c] = (cnt > 0) ? (un ? 1.0f / (float)cnt : 0.0f) : 0.25f;
        }

        float4 dot = make_float4(0,0,0,0);
        #pragma unroll
        for (int c = 0; c < NC_; ++c) {
            dot.x += Wn[c] * L[c].x; dot.y += Wn[c] * L[c].y;
            dot.z += Wn[c] * L[c].z; dot.w += Wn[c] * L[c].w;
        }
        float4 score = make_float4(Ptot.x * dot.x, Ptot.y * dot.y,
                                   Ptot.z * dot.z, Ptot.w * dot.w);

        float4 P = make_float4(0,0,0,0);
        #pragma unroll
        for (int k = 1; k < NC_; ++k) {
            f4acc(P, CS[k - 1]);
            float wd = Wn[k - 1] - Wn[k];
            if (wd != 0.0f) {
                score.x += wd * bnd[k - 1].x * P.x;
                score.y += wd * bnd[k - 1].y * P.y;
                score.z += wd * bnd[k - 1].z * P.z;
                score.w += wd * bnd[k - 1].w * P.w;
            }
        }

        out4[n * H4 + t] = make_float4(1.0f / (1.0f + expf(-score.x)),
                                       1.0f / (1.0f + expf(-score.y)),
                                       1.0f / (1.0f + expf(-score.z)),
                                       1.0f / (1.0f + expf(-score.w)));
    }

    __syncthreads();
    if (t == 0) g_cnt = 0;   // reset for next graph replay
}

extern "C" void kernel_launch(void* const* d_in, const int* in_sizes, int n_in,
                              void* d_out, int out_size) {
    const float* enc = (const float*)d_in[0];   // encoding (4096, 768)
    // d_in[1] = label_queries: provably unused (softmax over the note axis cancels scores)
    const float* lw  = (const float*)d_in[2];   // label_weights flat (768*8921)
    const void*  ids = d_in[3];                 // note_end_chunk_ids (4, int32 or int64)
    float* out = (float*)d_out;                 // (4, 768) float32

    fused_kernel<<<GRID, TPB>>>(enc, lw, ids, out);
}

// round 6
// speedup vs baseline: 1.4024x; 1.4024x over previous
#include <cuda_runtime.h>
#include <math.h>

constexpr int H_   = 768;
constexpr int NC_  = 8;       // chunks
constexpr int NL_  = 8921;    // labels
constexpr int NN_  = 4;       // notes
constexpr int JB_  = 1115;    // lw bucket width (8921 = 8*1115 + 1)

constexpr int ESEG  = 16;     // segments per encoding chunk
constexpr int EROWS = 32;     // 16*32 = 512 rows/chunk
constexpr int LSEG  = 32;     // segments per lw bucket
constexpr int LROWS = 35;     // 32*35 = 1120 >= 1116
constexpr int HG    = 3;      // 768 / 256 column groups
constexpr int ENC_BLOCKS = NC_ * ESEG * HG;   // 384
constexpr int LW_BLOCKS  = NC_ * LSEG * HG;   // 768
constexpr int GRID       = ENC_BLOCKS + LW_BLOCKS;  // 1152
constexpr int NGROUPS    = NC_ * HG * 2;      // 24 enc + 24 lw = 48

// Scratch (overwritten every call; counters reset by consumers -> replay-safe)
__device__ float g_pe[NC_ * ESEG * H_];   // encoding segment partials
__device__ float g_pl[NC_ * LSEG * H_];   // lw segment partials
__device__ float g_CS[NC_ * H_];          // per-chunk encoding column sums
__device__ float g_L [NC_ * H_];          // per-bucket lw column sums
__device__ unsigned int g_gc[NGROUPS];    // per-group arrival counters
__device__ unsigned int g_done;           // reducer arrival counter

__global__ __launch_bounds__(256) void fused_kernel(const float* __restrict__ enc,
                                                    const float* __restrict__ lw,
                                                    const void* __restrict__ idsRaw,
                                                    float* __restrict__ out) {
    const int b   = blockIdx.x;
    const int tid = threadIdx.x;

    // ---------------- Phase 1: streaming column block sums (R2-proven geometry) ----------------
    int grp, gsize, c_, hg_;
    if (b < ENC_BLOCKS) {
        int c   = b / (ESEG * HG);
        int rem = b % (ESEG * HG);
        int s   = rem / HG;
        int hg  = rem % HG;
        int h   = hg * 256 + tid;
        const float* p = enc + (size_t)(c * 512 + s * EROWS) * H_ + h;
        float a0 = 0.f, a1 = 0.f, a2 = 0.f, a3 = 0.f;
        #pragma unroll
        for (int r = 0; r < EROWS; r += 4) {
            a0 += p[(r + 0) * H_];
            a1 += p[(r + 1) * H_];
            a2 += p[(r + 2) * H_];
            a3 += p[(r + 3) * H_];
        }
        g_pe[(c * ESEG + s) * H_ + h] = (a0 + a1) + (a2 + a3);
        grp = c * HG + hg; gsize = ESEG; c_ = c; hg_ = hg;
    } else {
        int bb  = b - ENC_BLOCKS;
        int c   = bb / (LSEG * HG);
        int rem = bb % (LSEG * HG);
        int s   = rem / HG;
        int hg  = rem % HG;
        int h   = hg * 256 + tid;
        int r0   = c * JB_ + s * LROWS;
        int rend = min(r0 + LROWS, (c == NC_ - 1) ? NL_ : (c + 1) * JB_);
        float a0 = 0.f, a1 = 0.f, a2 = 0.f, a3 = 0.f;
        int r = r0;
        for (; r + 4 <= rend; r += 4) {
            a0 += lw[(size_t)(r + 0) * H_ + h];
            a1 += lw[(size_t)(r + 1) * H_ + h];
            a2 += lw[(size_t)(r + 2) * H_ + h];
            a3 += lw[(size_t)(r + 3) * H_ + h];
        }
        float tail = 0.f;
        for (; r < rend; ++r) tail += lw[(size_t)r * H_ + h];
        g_pl[(c * LSEG + s) * H_ + h] = ((a0 + a1) + (a2 + a3)) + tail;
        grp = NC_ * HG + c * HG + hg; gsize = LSEG; c_ = c; hg_ = hg;
    }

    // ---------------- Level A gate: last block of each group reduces it ----------------
    __threadfence();
    __syncthreads();
    __shared__ bool sIsRed;
    if (tid == 0)
        sIsRed = (atomicAdd(&g_gc[grp], 1u) == (unsigned)(gsize - 1));
    __syncthreads();
    if (!sIsRed) return;

    if (tid == 0) g_gc[grp] = 0;          // reset for next replay
    {
        int h = hg_ * 256 + tid;
        if (grp < NC_ * HG) {             // encoding group -> CS[c_]
            float s = 0.f;
            #pragma unroll
            for (int i = 0; i < ESEG; ++i) s += g_pe[(c_ * ESEG + i) * H_ + h];
            g_CS[c_ * H_ + h] = s;
        } else {                          // lw group -> L[c_]
            float s = 0.f;
            #pragma unroll
            for (int i = 0; i < LSEG; ++i) s += g_pl[(c_ * LSEG + i) * H_ + h];
            g_L[c_ * H_ + h] = s;
        }
    }

    // ---------------- Level B gate: last reducer runs the finale ----------------
    __threadfence();
    __syncthreads();
    __shared__ bool sIsFin;
    if (tid == 0)
        sIsFin = (atomicAdd(&g_done, 1u) == (unsigned)(NGROUPS - 1));
    __syncthreads();
    if (!sIsFin) return;

    if (tid == 0) g_done = 0;             // reset for next replay
    __threadfence();

    // ---- note_end_chunk_ids: detect int64 vs int32 layout ----
    const int* w = (const int*)idsRaw;
    int ids[NN_];
    {
        bool is64 = true;
        int v[NN_];
        #pragma unroll
        for (int i = 0; i < NN_; ++i) {
            int lo = w[2 * i], hi = w[2 * i + 1];
            v[i] = lo;
            if (hi != 0 || lo < 0 || lo >= NC_) is64 = false;
        }
        #pragma unroll
        for (int i = 0; i + 1 < NN_; ++i)
            if (v[i] > v[i + 1]) is64 = false;
        #pragma unroll
        for (int i = 0; i < NN_; ++i) ids[i] = is64 ? v[i] : w[i];
    }

    // ---- softmax weight table (4 notes x 8 chunks) ----
    float W[NN_][NC_];
    #pragma unroll
    for (int c = 0; c < NC_; ++c) {
        int cnt = 0;
        #pragma unroll
        for (int i = 0; i < NN_; ++i) cnt += (ids[i] < c) ? 1 : 0;
        #pragma unroll
        for (int n = 0; n < NN_; ++n) {
            bool un = (ids[n] < c);
            W[n][c] = (cnt > 0) ? (un ? 1.0f / (float)cnt : 0.0f) : 0.25f;
        }
    }

    // ---- per column-group finale (3 passes of 256 columns keeps regs low) ----
    for (int g = 0; g < HG; ++g) {
        int h = g * 256 + tid;
        float CS[NC_], L[NC_];
        #pragma unroll
        for (int c = 0; c < NC_; ++c) {
            CS[c] = g_CS[c * H_ + h];
            L[c]  = g_L [c * H_ + h];
        }
        float Ptot = 0.f;
        #pragma unroll
        for (int c = 0; c < NC_; ++c) Ptot += CS[c];

        float bnd[NC_ - 1];
        #pragma unroll
        for (int k = 1; k < NC_; ++k)
            bnd[k - 1] = lw[(size_t)(JB_ * k) * H_ + h];

        #pragma unroll
        for (int n = 0; n < NN_; ++n) {
            float dot = 0.f;
            #pragma unroll
            for (int c = 0; c < NC_; ++c) dot += W[n][c] * L[c];
            float score = Ptot * dot;

            // boundary corrections: j = 1115k straddles chunks (k-1, k) at prefix P[512k]
            float P = 0.f;
            #pragma unroll
            for (int k = 1; k < NC_; ++k) {
                P += CS[k - 1];
                float wd = W[n][k - 1] - W[n][k];
                score += wd * bnd[k - 1] * P;
            }
            out[n * H_ + h] = 1.0f / (1.0f + expf(-score));
        }
    }
}

extern "C" void kernel_launch(void* const* d_in, const int* in_sizes, int n_in,
                              void* d_out, int out_size) {
    const float* enc = (const float*)d_in[0];   // encoding (4096, 768)
    // d_in[1] = label_queries: provably unused (softmax over the note axis cancels scores)
    const float* lw  = (const float*)d_in[2];   // label_weights flat (768*8921)
    const void*  ids = d_in[3];                 // note_end_chunk_ids (4, int32 or int64)
    float* out = (float*)d_out;                 // (4, 768) float32

    fused_kernel<<<GRID, 256>>>(enc, lw, ids, out);
}

// round 7
// speedup vs baseline: 1.4839x; 1.0581x over previous
#include <cuda_runtime.h>
#include <math.h>

constexpr int H_   = 768;
constexpr int NC_  = 8;       // chunks
constexpr int NL_  = 8921;    // labels
constexpr int NN_  = 4;       // notes
constexpr int JB_  = 1115;    // lw bucket width (8921 = 8*1115 + 1)

constexpr int ESEG  = 16;     // segments per encoding chunk
constexpr int EROWS = 32;     // 16*32 = 512 rows/chunk
constexpr int LSEG  = 32;     // segments per lw bucket
constexpr int LROWS = 35;     // 32*35 = 1120 >= 1116
constexpr int HG    = 3;      // 768 / 256 column groups
constexpr int ENC_BLOCKS = NC_ * ESEG * HG;   // 384
constexpr int LW_BLOCKS  = NC_ * LSEG * HG;   // 768
constexpr int GRID       = ENC_BLOCKS + LW_BLOCKS;  // 1152
constexpr int NGROUPS    = NC_ * HG * 2;      // 24 enc + 24 lw = 48

// Scratch (overwritten every call; counters reset by consumers -> replay-safe)
__device__ float g_pe[NC_ * ESEG * H_];   // encoding segment partials
__device__ float g_pl[NC_ * LSEG * H_];   // lw segment partials
__device__ float g_CS[NC_ * H_];          // per-chunk encoding column sums
__device__ float g_L [NC_ * H_];          // per-bucket lw column sums
__device__ unsigned int g_gc[NGROUPS];    // per-group arrival counters
__device__ unsigned int g_done;           // reducer arrival counter

// min-blocks-per-SM = 8 forces <=32 regs: phase 1 (the BW-critical path) keeps
// full occupancy; any spills land only in the reducer/finale cold paths.
__global__ __launch_bounds__(256, 8) void fused_kernel(const float* __restrict__ enc,
                                                       const float* __restrict__ lw,
                                                       const void* __restrict__ idsRaw,
                                                       float* __restrict__ out) {
    const int b   = blockIdx.x;
    const int tid = threadIdx.x;

    // ---------------- Phase 1: streaming column block sums ----------------
    int grp, gsize, c_, hg_;
    if (b < ENC_BLOCKS) {
        int c   = b / (ESEG * HG);
        int rem = b % (ESEG * HG);
        int s   = rem / HG;
        int hg  = rem % HG;
        int h   = hg * 256 + tid;
        const float* p = enc + (size_t)(c * 512 + s * EROWS) * H_ + h;
        float a0 = 0.f, a1 = 0.f, a2 = 0.f, a3 = 0.f;
        #pragma unroll
        for (int r = 0; r < EROWS; r += 4) {
            a0 += p[(r + 0) * H_];
            a1 += p[(r + 1) * H_];
            a2 += p[(r + 2) * H_];
            a3 += p[(r + 3) * H_];
        }
        g_pe[(c * ESEG + s) * H_ + h] = (a0 + a1) + (a2 + a3);
        grp = c * HG + hg; gsize = ESEG; c_ = c; hg_ = hg;
    } else {
        int bb  = b - ENC_BLOCKS;
        int c   = bb / (LSEG * HG);
        int rem = bb % (LSEG * HG);
        int s   = rem / HG;
        int hg  = rem % HG;
        int h   = hg * 256 + tid;
        int r0   = c * JB_ + s * LROWS;
        int rend = min(r0 + LROWS, (c == NC_ - 1) ? NL_ : (c + 1) * JB_);
        float a0 = 0.f, a1 = 0.f, a2 = 0.f, a3 = 0.f;
        int r = r0;
        for (; r + 4 <= rend; r += 4) {
            a0 += lw[(size_t)(r + 0) * H_ + h];
            a1 += lw[(size_t)(r + 1) * H_ + h];
            a2 += lw[(size_t)(r + 2) * H_ + h];
            a3 += lw[(size_t)(r + 3) * H_ + h];
        }
        float tail = 0.f;
        for (; r < rend; ++r) tail += lw[(size_t)r * H_ + h];
        g_pl[(c * LSEG + s) * H_ + h] = ((a0 + a1) + (a2 + a3)) + tail;
        grp = NC_ * HG + c * HG + hg; gsize = LSEG; c_ = c; hg_ = hg;
    }

    // ---------------- Level A gate: last block of each group reduces it ----------------
    __threadfence();
    __syncthreads();
    __shared__ bool sIsRed;
    if (tid == 0)
        sIsRed = (atomicAdd(&g_gc[grp], 1u) == (unsigned)(gsize - 1));
    __syncthreads();
    if (!sIsRed) return;

    if (tid == 0) g_gc[grp] = 0;          // reset for next replay
    {
        int h = hg_ * 256 + tid;
        if (grp < NC_ * HG) {             // encoding group -> CS[c_]
            float s = 0.f;
            #pragma unroll
            for (int i = 0; i < ESEG; ++i) s += g_pe[(c_ * ESEG + i) * H_ + h];
            g_CS[c_ * H_ + h] = s;
        } else {                          // lw group -> L[c_]
            float s = 0.f;
            #pragma unroll
            for (int i = 0; i < LSEG; ++i) s += g_pl[(c_ * LSEG + i) * H_ + h];
            g_L[c_ * H_ + h] = s;
        }
    }

    // ---------------- Level B gate: last reducer runs the finale ----------------
    __threadfence();
    __syncthreads();
    __shared__ bool sIsFin;
    if (tid == 0)
        sIsFin = (atomicAdd(&g_done, 1u) == (unsigned)(NGROUPS - 1));
    __syncthreads();
    if (!sIsFin) return;

    if (tid == 0) g_done = 0;             // reset for next replay

    // ---- note_end_chunk_ids: detect int64 vs int32 layout ----
    const int* w = (const int*)idsRaw;
    int ids[NN_];
    {
        bool is64 = true;
        int v[NN_];
        #pragma unroll
        for (int i = 0; i < NN_; ++i) {
            int lo = w[2 * i], hi = w[2 * i + 1];
            v[i] = lo;
            if (hi != 0 || lo < 0 || lo >= NC_) is64 = false;
        }
        #pragma unroll
        for (int i = 0; i + 1 < NN_; ++i)
            if (v[i] > v[i + 1]) is64 = false;
        #pragma unroll
        for (int i = 0; i < NN_; ++i) ids[i] = is64 ? v[i] : w[i];
    }

    // ---- per column-group finale (cold path; spills are fine) ----
    for (int g = 0; g < HG; ++g) {
        int h = g * 256 + tid;
        float CS[NC_], L[NC_];
        #pragma unroll
        for (int c = 0; c < NC_; ++c) {
            CS[c] = g_CS[c * H_ + h];
            L[c]  = g_L [c * H_ + h];
        }
        float Ptot = 0.f;
        #pragma unroll
        for (int c = 0; c < NC_; ++c) Ptot += CS[c];

        #pragma unroll
        for (int n = 0; n < NN_; ++n) {
            // softmax weight row for this note: masked(n,c) <=> c <= ids[n]
            float Wn[NC_];
            #pragma unroll
            for (int c = 0; c < NC_; ++c) {
                int cnt = 0;
                #pragma unroll
                for (int i = 0; i < NN_; ++i) cnt += (ids[i] < c) ? 1 : 0;
                bool un = (ids[n] < c);
                Wn[c] = (cnt > 0) ? (un ? 1.0f / (float)cnt : 0.0f) : 0.25f;
            }

            float dot = 0.f;
            #pragma unroll
            for (int c = 0; c < NC_; ++c) dot += Wn[c] * L[c];
            float score = Ptot * dot;

            // boundary corrections: j = 1115k straddles chunks (k-1, k) at prefix P[512k]
            float P = 0.f;
            #pragma unroll
            for (int k = 1; k < NC_; ++k) {
                P += CS[k - 1];
                float wd = Wn[k - 1] - Wn[k];
                score += wd * lw[(size_t)(JB_ * k) * H_ + h] * P;
            }
            out[n * H_ + h] = 1.0f / (1.0f + expf(-score));
        }
    }
}

extern "C" void kernel_launch(void* const* d_in, const int* in_sizes, int n_in,
                              void* d_out, int out_size) {
    const float* enc = (const float*)d_in[0];   // encoding (4096, 768)
    // d_in[1] = label_queries: provably unused (softmax over the note axis cancels scores)
    const float* lw  = (const float*)d_in[2];   // label_weights flat (768*8921)
    const void*  ids = d_in[3];                 // note_end_chunk_ids (4, int32 or int64)
    float* out = (float*)d_out;                 // (4, 768) float32

    fused_kernel<<<GRID, 256>>>(enc, lw, ids, out);
}

// round 8
// speedup vs baseline: 1.9492x; 1.3136x over previous
#include <cuda_runtime.h>
#include <math.h>

constexpr int H_   = 768;
constexpr int NC_  = 8;       // chunks
constexpr int NL_  = 8921;    // labels
constexpr int NN_  = 4;       // notes
constexpr int JB_  = 1115;    // lw bucket width (8921 = 8*1115 + 1)

constexpr int ESEG  = 16;     // segments per encoding chunk
constexpr int EROWS = 32;     // 16*32 = 512 rows/chunk
constexpr int LSEG  = 32;     // segments per lw bucket
constexpr int LROWS = 35;     // 32*35 = 1120 >= 1116
constexpr int HG    = 3;      // 768 / 256 column groups
constexpr int ENC_BLOCKS = NC_ * ESEG * HG;   // 384
constexpr int LW_BLOCKS  = NC_ * LSEG * HG;   // 768
constexpr int GRID       = ENC_BLOCKS + LW_BLOCKS;  // 1152
constexpr int NGROUPS    = NC_ * HG * 2;      // 24 enc + 24 lw = 48

// Scratch (overwritten every call; counters reset by their consumers -> replay-safe)
__device__ float g_pe[NC_ * ESEG * H_];   // encoding segment partials
__device__ float g_pl[NC_ * LSEG * H_];   // lw segment partials
__device__ float g_CS[NC_ * H_];          // per-chunk encoding column sums
__device__ float g_L [NC_ * H_];          // per-bucket lw column sums
__device__ unsigned int g_gc[NGROUPS];    // per-group arrival counters

// Release-or-acquire RMW at gpu scope: orders this thread's (and, via the CTA
// barrier happens-before chain, the whole block's) prior global stores without
// MEMBAR.GPU's CCTL.IVALL L1-flush.
__device__ __forceinline__ unsigned int gate_add_acq_rel(unsigned int* p) {
    unsigned int old;
    asm volatile("atom.acq_rel.gpu.global.add.u32 %0, [%1], %2;"
                 : "=r"(old) : "l"(p), "r"(1u) : "memory");
    return old;
}

// ---------------- Kernel 1: streaming block sums + in-kernel group reduction ----------------
__global__ __launch_bounds__(256, 8) void sum_kernel(const float* __restrict__ enc,
                                                     const float* __restrict__ lw) {
    const int b   = blockIdx.x;
    const int tid = threadIdx.x;

    int grp, gsize, c_, hg_;
    if (b < ENC_BLOCKS) {
        int c   = b / (ESEG * HG);
        int rem = b % (ESEG * HG);
        int s   = rem / HG;
        int hg  = rem % HG;
        int h   = hg * 256 + tid;
        const float* p = enc + (size_t)(c * 512 + s * EROWS) * H_ + h;
        float a0 = 0.f, a1 = 0.f, a2 = 0.f, a3 = 0.f;
        #pragma unroll
        for (int r = 0; r < EROWS; r += 4) {
            a0 += p[(r + 0) * H_];
            a1 += p[(r + 1) * H_];
            a2 += p[(r + 2) * H_];
            a3 += p[(r + 3) * H_];
        }
        g_pe[(c * ESEG + s) * H_ + h] = (a0 + a1) + (a2 + a3);
        grp = c * HG + hg; gsize = ESEG; c_ = c; hg_ = hg;
    } else {
        int bb  = b - ENC_BLOCKS;
        int c   = bb / (LSEG * HG);
        int rem = bb % (LSEG * HG);
        int s   = rem / HG;
        int hg  = rem % HG;
        int h   = hg * 256 + tid;
        int r0   = c * JB_ + s * LROWS;
        int rend = min(r0 + LROWS, (c == NC_ - 1) ? NL_ : (c + 1) * JB_);
        float a0 = 0.f, a1 = 0.f, a2 = 0.f, a3 = 0.f;
        int r = r0;
        for (; r + 4 <= rend; r += 4) {
            a0 += lw[(size_t)(r + 0) * H_ + h];
            a1 += lw[(size_t)(r + 1) * H_ + h];
            a2 += lw[(size_t)(r + 2) * H_ + h];
            a3 += lw[(size_t)(r + 3) * H_ + h];
        }
        float tail = 0.f;
        for (; r < rend; ++r) tail += lw[(size_t)r * H_ + h];
        g_pl[(c * LSEG + s) * H_ + h] = ((a0 + a1) + (a2 + a3)) + tail;
        grp = NC_ * HG + c * HG + hg; gsize = LSEG; c_ = c; hg_ = hg;
    }

    // Group gate: last-arriving block of each group reduces its segments.
    __syncthreads();                         // block's stores happen-before tid0's release RMW
    __shared__ bool sIsRed;
    if (tid == 0)
        sIsRed = (gate_add_acq_rel(&g_gc[grp]) == (unsigned)(gsize - 1));
    __syncthreads();
    if (!sIsRed) return;

    if (tid == 0) g_gc[grp] = 0;             // all group members already arrived; replay-safe
    int h = hg_ * 256 + tid;
    if (grp < NC_ * HG) {                    // encoding group -> CS[c_]
        float s = 0.f;
        #pragma unroll
        for (int i = 0; i < ESEG; ++i) s += g_pe[(c_ * ESEG + i) * H_ + h];
        g_CS[c_ * H_ + h] = s;
    } else {                                 // lw group -> L[c_]
        float s = 0.f;
        #pragma unroll
        for (int i = 0; i < LSEG; ++i) s += g_pl[(c_ * LSEG + i) * H_ + h];
        g_L[c_ * H_ + h] = s;
    }
}

// ---------------- Kernel 2: tiny combine (reads only 48KB of CS/L + 7 lw rows) ----------------
__global__ __launch_bounds__(128) void final2_kernel(const float* __restrict__ lw,
                                                     const void* __restrict__ idsRaw,
                                                     float* __restrict__ out) {
    const int h = blockIdx.x * 128 + threadIdx.x;   // one column per thread, 768 total

    float CS[NC_], L[NC_], bnd[NC_ - 1];
    #pragma unroll
    for (int c = 0; c < NC_; ++c) {
        CS[c] = g_CS[c * H_ + h];
        L[c]  = g_L [c * H_ + h];
    }
    #pragma unroll
    for (int k = 1; k < NC_; ++k)
        bnd[k - 1] = lw[(size_t)(JB_ * k) * H_ + h];

    // note_end_chunk_ids: detect int64 vs int32 layout
    const int* w = (const int*)idsRaw;
    int ids[NN_];
    {
        bool is64 = true;
        int v[NN_];
        #pragma unroll
        for (int i = 0; i < NN_; ++i) {
            int lo = w[2 * i], hi = w[2 * i + 1];
            v[i] = lo;
            if (hi != 0 || lo < 0 || lo >= NC_) is64 = false;
        }
        #pragma unroll
        for (int i = 0; i + 1 < NN_; ++i)
            if (v[i] > v[i + 1]) is64 = false;
        #pragma unroll
        for (int i = 0; i < NN_; ++i) ids[i] = is64 ? v[i] : w[i];
    }

    float Ptot = 0.f;
    #pragma unroll
    for (int c = 0; c < NC_; ++c) Ptot += CS[c];

    #pragma unroll
    for (int n = 0; n < NN_; ++n) {
        // softmax weight row: masked(n,c) <=> c <= ids[n]; count = #{i: ids[i] < c}
        float Wn[NC_];
        #pragma unroll
        for (int c = 0; c < NC_; ++c) {
            int cnt = 0;
            #pragma unroll
            for (int i = 0; i < NN_; ++i) cnt += (ids[i] < c) ? 1 : 0;
            bool un = (ids[n] < c);
            Wn[c] = (cnt > 0) ? (un ? 1.0f / (float)cnt : 0.0f) : 0.25f;
        }

        float dot = 0.f;
        #pragma unroll
        for (int c = 0; c < NC_; ++c) dot += Wn[c] * L[c];
        float score = Ptot * dot;

        // boundary corrections: j = 1115k straddles chunks (k-1, k) at prefix P[512k]
        float P = 0.f;
        #pragma unroll
        for (int k = 1; k < NC_; ++k) {
            P += CS[k - 1];
            float wd = Wn[k - 1] - Wn[k];
            score += wd * bnd[k - 1] * P;
        }
        out[n * H_ + h] = 1.0f / (1.0f + expf(-score));
    }
}

extern "C" void kernel_launch(void* const* d_in, const int* in_sizes, int n_in,
                              void* d_out, int out_size) {
    const float* enc = (const float*)d_in[0];   // encoding (4096, 768)
    // d_in[1] = label_queries: provably unused (softmax over the note axis cancels scores)
    const float* lw  = (const float*)d_in[2];   // label_weights flat (768*8921)
    const void*  ids = d_in[3];                 // note_end_chunk_ids (4, int32 or int64)
    float* out = (float*)d_out;                 // (4, 768) float32

    sum_kernel<<<GRID, 256>>>(enc, lw);
    final2_kernel<<<H_ / 128, 128>>>(lw, ids, out);
}

// round 10
// speedup vs baseline: 2.2494x; 1.1540x over previous
#include <cuda_runtime.h>
#include <math.h>

constexpr int H_   = 768;
constexpr int NC_  = 8;       // chunks
constexpr int NL_  = 8921;    // labels
constexpr int NN_  = 4;       // notes
constexpr int JB_  = 1115;    // lw bucket width (8921 = 8*1115 + 1)

constexpr int ESEG  = 16;     // segments per encoding chunk
constexpr int EROWS = 32;     // 16*32 = 512 rows/chunk
constexpr int LSEG  = 32;     // segments per lw bucket
constexpr int LROWS = 35;     // 32*35 = 1120 >= 1116
constexpr int HG    = 3;      // 768 / 256 column groups
constexpr int ENC_BLOCKS = NC_ * ESEG * HG;   // 384
constexpr int LW_BLOCKS  = NC_ * LSEG * HG;   // 768
constexpr int GRID       = ENC_BLOCKS + LW_BLOCKS;  // 1152

// Accumulators. Zero at module load; final2_kernel re-zeroes exactly the slots
// it consumed -> invariant "zero on entry to sum_kernel" holds on every graph
// replay. No counters, no gates, no fences.
__device__ float g_CS[NC_ * H_];          // per-chunk encoding column sums
__device__ float g_L [NC_ * H_];          // per-bucket lw column sums

__device__ __forceinline__ void redg_add(float* p, float v) {
    asm volatile("red.relaxed.gpu.global.add.f32 [%0], %1;" :: "l"(p), "f"(v) : "memory");
}

// ---------------- Kernel 1: pure streaming block sums + one REDG per thread ----------------
__global__ __launch_bounds__(256, 8) void sum_kernel(const float* __restrict__ enc,
                                                     const float* __restrict__ lw) {
    const int b   = blockIdx.x;
    const int tid = threadIdx.x;

    if (b < ENC_BLOCKS) {
        int c   = b / (ESEG * HG);
        int rem = b % (ESEG * HG);
        int s   = rem / HG;
        int hg  = rem % HG;
        int h   = hg * 256 + tid;
        const float* p = enc + (size_t)(c * 512 + s * EROWS) * H_ + h;
        float a0 = 0.f, a1 = 0.f, a2 = 0.f, a3 = 0.f;
        #pragma unroll
        for (int r = 0; r < EROWS; r += 4) {
            a0 += p[(r + 0) * H_];
            a1 += p[(r + 1) * H_];
            a2 += p[(r + 2) * H_];
            a3 += p[(r + 3) * H_];
        }
        redg_add(&g_CS[c * H_ + h], (a0 + a1) + (a2 + a3));
    } else {
        int bb  = b - ENC_BLOCKS;
        int c   = bb / (LSEG * HG);
        int rem = bb % (LSEG * HG);
        int s   = rem / HG;
        int hg  = rem % HG;
        int h   = hg * 256 + tid;
        int r0   = c * JB_ + s * LROWS;
        int rend = min(r0 + LROWS, (c == NC_ - 1) ? NL_ : (c + 1) * JB_);
        float a0 = 0.f, a1 = 0.f, a2 = 0.f, a3 = 0.f;
        int r = r0;
        for (; r + 4 <= rend; r += 4) {
            a0 += lw[(size_t)(r + 0) * H_ + h];
            a1 += lw[(size_t)(r + 1) * H_ + h];
            a2 += lw[(size_t)(r + 2) * H_ + h];
            a3 += lw[(size_t)(r + 3) * H_ + h];
        }
        float tail = 0.f;
        for (; r < rend; ++r) tail += lw[(size_t)r * H_ + h];
        redg_add(&g_L[c * H_ + h], ((a0 + a1) + (a2 + a3)) + tail);
    }
}

// ---------------- Kernel 2: combine + sigmoid + self-rezero of accumulators ----------------
__global__ __launch_bounds__(128) void final2_kernel(const float* __restrict__ lw,
                                                     const void* __restrict__ idsRaw,
                                                     float* __restrict__ out) {
    const int h = blockIdx.x * 128 + threadIdx.x;   // one column per thread, 768 total

    float CS[NC_], L[NC_], bnd[NC_ - 1];
    #pragma unroll
    for (int c = 0; c < NC_; ++c) {
        CS[c] = g_CS[c * H_ + h];
        L[c]  = g_L [c * H_ + h];
    }
    // Re-zero for the next replay: each thread clears exactly the slots it read.
    #pragma unroll
    for (int c = 0; c < NC_; ++c) {
        g_CS[c * H_ + h] = 0.f;
        g_L [c * H_ + h] = 0.f;
    }
    #pragma unroll
    for (int k = 1; k < NC_; ++k)
        bnd[k - 1] = lw[(size_t)(JB_ * k) * H_ + h];

    // note_end_chunk_ids: detect int64 vs int32 layout
    const int* w = (const int*)idsRaw;
    int ids[NN_];
    {
        bool is64 = true;
        int v[NN_];
        #pragma unroll
        for (int i = 0; i < NN_; ++i) {
            int lo = w[2 * i], hi = w[2 * i + 1];
            v[i] = lo;
            if (hi != 0 || lo < 0 || lo >= NC_) is64 = false;
        }
        #pragma unroll
        for (int i = 0; i + 1 < NN_; ++i)
            if (v[i] > v[i + 1]) is64 = false;
        #pragma unroll
        for (int i = 0; i < NN_; ++i) ids[i] = is64 ? v[i] : w[i];
    }

    float Ptot = 0.f;
    #pragma unroll
    for (int c = 0; c < NC_; ++c) Ptot += CS[c];

    #pragma unroll
    for (int n = 0; n < NN_; ++n) {
        // softmax weight row: masked(n,c) <=> c <= ids[n]; count = #{i: ids[i] < c}
        float Wn[NC_];
        #pragma unroll
        for (int c = 0; c < NC_; ++c) {
            int cnt = 0;
            #pragma unroll
            for (int i = 0; i < NN_; ++i) cnt += (ids[i] < c) ? 1 : 0;
            bool un = (ids[n] < c);
            Wn[c] = (cnt > 0) ? (un ? 1.0f / (float)cnt : 0.0f) : 0.25f;
        }

        float dot = 0.f;
        #pragma unroll
        for (int c = 0; c < NC_; ++c) dot += Wn[c] * L[c];
        float score = Ptot * dot;

        // boundary corrections: j = 1115k straddles chunks (k-1, k) at prefix P[512k]
        float P = 0.f;
        #pragma unroll
        for (int k = 1; k < NC_; ++k) {
            P += CS[k - 1];
            float wd = Wn[k - 1] - Wn[k];
            score += wd * bnd[k - 1] * P;
        }
        out[n * H_ + h] = 1.0f / (1.0f + expf(-score));
    }
}

extern "C" void kernel_launch(void* const* d_in, const int* in_sizes, int n_in,
                              void* d_out, int out_size) {
    const float* enc = (const float*)d_in[0];   // encoding (4096, 768)
    // d_in[1] = label_queries: provably unused (softmax over the note axis cancels scores)
    const float* lw  = (const float*)d_in[2];   // label_weights flat (768*8921)
    const void*  ids = d_in[3];                 // note_end_chunk_ids (4, int32 or int64)
    float* out = (float*)d_out;                 // (4, 768) float32

    sum_kernel<<<GRID, 256>>>(enc, lw);
    final2_kernel<<<H_ / 128, 128>>>(lw, ids, out);
}